// round 4
// baseline (speedup 1.0000x reference)
#include <cuda_runtime.h>
#include <math.h>

#define BB 4
#define NN 2048
#define DD 1024
#define EE 8
#define BT 128
#define TOPK 2
#define NTOK (BB*NN)
#define GM_K 16

// ---------------- scratch (device globals; no allocations allowed) ----------------
__device__ __align__(16) float g_h [BB*EE*NN*BT];   // 32 MB (h, then reused for attn out)
__device__ __align__(16) float g_q [BB*EE*NN*BT];
__device__ __align__(16) float g_k [BB*EE*NN*BT];
__device__ __align__(16) float g_v [BB*EE*NN*BT];
__device__ float g_gatew[NTOK*EE];
__device__ unsigned char g_slot[NTOK*EE];
__device__ int   g_idx[BB*EE*NN];
__device__ int   g_cnt[BB*EE];
__device__ float g_pmean[EE];
__device__ __align__(16) float g_ybuf[(size_t)NTOK*2*DD];

// ---------------- router ----------------
__global__ __launch_bounds__(256) void router_kernel(const float* __restrict__ x,
                                                     const float* __restrict__ Wg) {
    __shared__ float blk[EE];
    int tid = threadIdx.x;
    if (tid < EE) blk[tid] = 0.f;
    __syncthreads();
    int token = blockIdx.x * 8 + (tid >> 5);
    int lane = tid & 31;
    float acc[EE];
#pragma unroll
    for (int e = 0; e < EE; e++) acc[e] = 0.f;
    const float* xr = x + (size_t)token * DD;
    for (int d = lane; d < DD; d += 32) {
        float xv = xr[d];
        const float* w = Wg + d * EE;
#pragma unroll
        for (int e = 0; e < EE; e++) acc[e] += xv * w[e];
    }
#pragma unroll
    for (int off = 16; off; off >>= 1)
#pragma unroll
        for (int e = 0; e < EE; e++) acc[e] += __shfl_xor_sync(0xffffffffu, acc[e], off);
    if (lane == 0) {
        float m = acc[0];
#pragma unroll
        for (int e = 1; e < EE; e++) m = fmaxf(m, acc[e]);
        float p[EE], s = 0.f;
#pragma unroll
        for (int e = 0; e < EE; e++) { p[e] = expf(acc[e] - m); s += p[e]; }
        float inv = 1.f / s;
#pragma unroll
        for (int e = 0; e < EE; e++) p[e] *= inv;
        int i1 = 0;
#pragma unroll
        for (int e = 1; e < EE; e++) if (p[e] > p[i1]) i1 = e;
        int i2 = (i1 == 0) ? 1 : 0;
#pragma unroll
        for (int e = 0; e < EE; e++) if (e != i1 && p[e] > p[i2]) i2 = e;
        float wsum = p[i1] + p[i2];
        float w1 = p[i1] / wsum, w2 = p[i2] / wsum;
#pragma unroll
        for (int e = 0; e < EE; e++) { g_gatew[token*EE+e] = 0.f; g_slot[token*EE+e] = 0xFF; }
        g_gatew[token*EE+i1] = w1; g_slot[token*EE+i1] = 0;
        g_gatew[token*EE+i2] = w2; g_slot[token*EE+i2] = 1;
#pragma unroll
        for (int e = 0; e < EE; e++) atomicAdd(&blk[e], p[e]);
    }
    __syncthreads();
    if (tid < EE) atomicAdd(&g_pmean[tid], blk[tid]);
}

__global__ void zero_pmean_kernel() {
    if (threadIdx.x < EE) g_pmean[threadIdx.x] = 0.f;
}

// ---------------- ordered compaction per (b,e) ----------------
__global__ __launch_bounds__(256) void compact_kernel() {
    int e = blockIdx.x, b = blockIdx.y;
    int tid = threadIdx.x, lane = tid & 31, w = tid >> 5;
    __shared__ int wsum[8];
    int base = 0;
    for (int start = 0; start < NN; start += 256) {
        int t = start + tid;
        int f = (g_slot[(size_t)(b*NN + t)*EE + e] != 0xFF) ? 1 : 0;
        unsigned bal = __ballot_sync(0xffffffffu, f);
        int wpre = __popc(bal & ((1u << lane) - 1u));
        if (lane == 0) wsum[w] = __popc(bal);
        __syncthreads();
        int woff = 0, tot = 0;
#pragma unroll
        for (int i = 0; i < 8; i++) { int s = wsum[i]; if (i < w) woff += s; tot += s; }
        if (f) g_idx[(size_t)(b*EE + e)*NN + base + woff + wpre] = t;
        base += tot;
        __syncthreads();
    }
    if (tid == 0) g_cnt[b*EE + e] = base;
}

// ---------------- scalar outputs ----------------
__global__ void scalars_kernel(float* __restrict__ out, int out_size) {
    int tid = threadIdx.x;
    float frac = 0.f, pm = 0.f;
    if (tid < EE) {
        int c = 0;
        for (int b = 0; b < BB; b++) c += g_cnt[b*EE + tid];
        frac = (float)c / (float)NTOK;
        pm = g_pmean[tid] / (float)NTOK;
    }
    float prod = frac * pm, mx = frac;
#pragma unroll
    for (int off = 16; off; off >>= 1) {
        prod += __shfl_xor_sync(0xffffffffu, prod, off);
        mx = fmaxf(mx, __shfl_xor_sync(0xffffffffu, mx, off));
    }
    if (tid == 0 && out_size >= NTOK*DD + 2) {
        out[out_size - 2] = ((float)EE / (float)TOPK) * prod;
        out[out_size - 1] = mx / ((float)TOPK / (float)EE) - 1.f;
    }
}

// ======== 128x128 SGEMM core (shared by down / qkv / up) ========
// 256 threads; each owns an 8x8 accumulator (four 4x4 quadrants).
// As[k][row] transposed, stride 132 (16B aligned rows, mild store conflicts only).
#define SGEMM_DECLS \
    __shared__ float As[GM_K][132]; \
    __shared__ float Bs[GM_K][128]; \
    int tid = threadIdx.x, tx = tid & 15, ty = tid >> 4; \
    int arow0 = tid >> 2, ac4 = tid & 3; \
    int bk0 = tid >> 5, bn4 = tid & 31; \
    float acc[2][2][4][4] = {};

#define SGEMM_STORE_TILE(aR0, aR1, bR0, bR1) \
    { \
        As[ac4*4+0][arow0] = aR0.x; As[ac4*4+1][arow0] = aR0.y; \
        As[ac4*4+2][arow0] = aR0.z; As[ac4*4+3][arow0] = aR0.w; \
        As[ac4*4+0][64+arow0] = aR1.x; As[ac4*4+1][64+arow0] = aR1.y; \
        As[ac4*4+2][64+arow0] = aR1.z; As[ac4*4+3][64+arow0] = aR1.w; \
        *(float4*)&Bs[bk0][bn4*4]   = bR0; \
        *(float4*)&Bs[8+bk0][bn4*4] = bR1; \
    }

#define SGEMM_COMPUTE \
    _Pragma("unroll") \
    for (int kk = 0; kk < GM_K; kk++) { \
        float4 a0 = *(const float4*)&As[kk][ty*4]; \
        float4 a1 = *(const float4*)&As[kk][64+ty*4]; \
        float4 b0 = *(const float4*)&Bs[kk][tx*4]; \
        float4 b1 = *(const float4*)&Bs[kk][64+tx*4]; \
        float av[2][4] = {{a0.x,a0.y,a0.z,a0.w},{a1.x,a1.y,a1.z,a1.w}}; \
        float bv[2][4] = {{b0.x,b0.y,b0.z,b0.w},{b1.x,b1.y,b1.z,b1.w}}; \
        _Pragma("unroll") \
        for (int mq = 0; mq < 2; mq++) \
        _Pragma("unroll") \
        for (int j = 0; j < 4; j++) \
        _Pragma("unroll") \
        for (int nq = 0; nq < 2; nq++) \
        _Pragma("unroll") \
        for (int u = 0; u < 4; u++) \
            acc[mq][nq][j][u] += av[mq][j] * bv[nq][u]; \
    }

static __device__ __forceinline__ float4 f4zero() { return make_float4(0.f,0.f,0.f,0.f); }

// ---------------- down: h = gather(x) @ W_down[e]  (M=cnt tile 128, N=128, K=1024) ----------------
__global__ __launch_bounds__(256) void down_kernel(const float* __restrict__ x,
                                                   const float* __restrict__ Wd) {
    int e = blockIdx.y, b = blockIdx.z;
    int cnt = g_cnt[b*EE + e];
    int rowbase = blockIdx.x * 128;
    if (rowbase >= cnt) return;
    SGEMM_DECLS
    const int* idx = g_idx + (size_t)(b*EE + e)*NN;
    const float* ap0 = (rowbase + arow0 < cnt)
        ? x + (size_t)(b*NN + idx[rowbase + arow0])*DD + ac4*4 : (const float*)0;
    const float* ap1 = (rowbase + 64 + arow0 < cnt)
        ? x + (size_t)(b*NN + idx[rowbase + 64 + arow0])*DD + ac4*4 : (const float*)0;
    const float* wp = Wd + (size_t)e*DD*BT;
    float4 aR0 = ap0 ? *(const float4*)ap0 : f4zero();
    float4 aR1 = ap1 ? *(const float4*)ap1 : f4zero();
    float4 bR0 = *(const float4*)(wp + (size_t)bk0*BT + bn4*4);
    float4 bR1 = *(const float4*)(wp + (size_t)(8+bk0)*BT + bn4*4);
    const int nk = DD / GM_K;
    for (int t = 0; t < nk; t++) {
        __syncthreads();
        SGEMM_STORE_TILE(aR0, aR1, bR0, bR1)
        __syncthreads();
        if (t + 1 < nk) {
            int k0 = (t+1)*GM_K;
            aR0 = ap0 ? *(const float4*)(ap0 + k0) : f4zero();
            aR1 = ap1 ? *(const float4*)(ap1 + k0) : f4zero();
            bR0 = *(const float4*)(wp + (size_t)(k0+bk0)*BT + bn4*4);
            bR1 = *(const float4*)(wp + (size_t)(k0+8+bk0)*BT + bn4*4);
        }
        SGEMM_COMPUTE
    }
    float* hp = g_h + ((size_t)(b*EE + e)*NN + rowbase)*BT;
#pragma unroll
    for (int mq = 0; mq < 2; mq++)
#pragma unroll
    for (int j = 0; j < 4; j++) {
        int r = mq*64 + ty*4 + j;
        if (rowbase + r < cnt) {
            *(float4*)&hp[(size_t)r*BT + tx*4]      = make_float4(acc[mq][0][j][0],acc[mq][0][j][1],acc[mq][0][j][2],acc[mq][0][j][3]);
            *(float4*)&hp[(size_t)r*BT + 64 + tx*4] = make_float4(acc[mq][1][j][0],acc[mq][1][j][1],acc[mq][1][j][2],acc[mq][1][j][3]);
        }
    }
}

// ---------------- qkv: {q,k,v} = h @ W_{q,k,v}[e]  (K=128) ----------------
__global__ __launch_bounds__(256) void qkv_kernel(const float* __restrict__ Wq,
                                                  const float* __restrict__ Wk,
                                                  const float* __restrict__ Wv) {
    int sel = blockIdx.y / EE, e = blockIdx.y % EE, b = blockIdx.z;
    int cnt = g_cnt[b*EE + e];
    int rowbase = blockIdx.x * 128;
    if (rowbase >= cnt) return;
    SGEMM_DECLS
    const float* W = (sel == 0) ? Wq : (sel == 1) ? Wk : Wv;
    float* outp = (sel == 0) ? g_q : (sel == 1) ? g_k : g_v;
    const float* A = g_h + ((size_t)(b*EE + e)*NN + rowbase)*BT;
    const float* ap0 = (rowbase + arow0 < cnt)      ? A + (size_t)arow0*BT + ac4*4        : (const float*)0;
    const float* ap1 = (rowbase + 64 + arow0 < cnt) ? A + (size_t)(64+arow0)*BT + ac4*4   : (const float*)0;
    const float* wp = W + (size_t)e*BT*BT;
    float4 aR0 = ap0 ? *(const float4*)ap0 : f4zero();
    float4 aR1 = ap1 ? *(const float4*)ap1 : f4zero();
    float4 bR0 = *(const float4*)(wp + (size_t)bk0*BT + bn4*4);
    float4 bR1 = *(const float4*)(wp + (size_t)(8+bk0)*BT + bn4*4);
    const int nk = BT / GM_K;
    for (int t = 0; t < nk; t++) {
        __syncthreads();
        SGEMM_STORE_TILE(aR0, aR1, bR0, bR1)
        __syncthreads();
        if (t + 1 < nk) {
            int k0 = (t+1)*GM_K;
            aR0 = ap0 ? *(const float4*)(ap0 + k0) : f4zero();
            aR1 = ap1 ? *(const float4*)(ap1 + k0) : f4zero();
            bR0 = *(const float4*)(wp + (size_t)(k0+bk0)*BT + bn4*4);
            bR1 = *(const float4*)(wp + (size_t)(k0+8+bk0)*BT + bn4*4);
        }
        SGEMM_COMPUTE
    }
    float* op = outp + ((size_t)(b*EE + e)*NN + rowbase)*BT;
#pragma unroll
    for (int mq = 0; mq < 2; mq++)
#pragma unroll
    for (int j = 0; j < 4; j++) {
        int r = mq*64 + ty*4 + j;
        if (rowbase + r < cnt) {
            *(float4*)&op[(size_t)r*BT + tx*4]      = make_float4(acc[mq][0][j][0],acc[mq][0][j][1],acc[mq][0][j][2],acc[mq][0][j][3]);
            *(float4*)&op[(size_t)r*BT + 64 + tx*4] = make_float4(acc[mq][1][j][0],acc[mq][1][j][1],acc[mq][1][j][2],acc[mq][1][j][3]);
        }
    }
}

// ---------------- flash attention over compact rows (unchanged from R3) ----------------
#define KST_STRIDE 68
#define PS_STRIDE 68
#define ATTN_SMEM_FLOATS (64*128 + 128*KST_STRIDE + 64*128 + 64*PS_STRIDE)

__global__ __launch_bounds__(256) void attn_kernel() {
    int e = blockIdx.y, b = blockIdx.z;
    int cnt = g_cnt[b*EE + e];
    int rowbase = blockIdx.x * 64;
    if (rowbase >= cnt) return;
    extern __shared__ float smf[];
    float* qs  = smf;
    float* kst = qs + 64*128;
    float* vs  = kst + 128*KST_STRIDE;
    float* ps  = vs + 64*128;
    int tid = threadIdx.x, tx = tid & 15, ty = tid >> 4;
    int c4 = tid & 31, r0 = tid >> 5;
    size_t base = (size_t)(b*EE + e)*NN*BT;
    const float* qg = g_q + base + (size_t)rowbase*BT;
#pragma unroll
    for (int i = 0; i < 8; i++) {
        int r = r0 + 8*i;
        float4 val = (rowbase + r < cnt) ? ((const float4*)(qg + (size_t)r*BT))[c4]
                                         : make_float4(0.f,0.f,0.f,0.f);
        ((float4*)(qs + r*BT))[c4] = val;
    }
    float m_i[4], l_i[4], o[4][8];
#pragma unroll
    for (int j = 0; j < 4; j++) {
        m_i[j] = -1e30f; l_i[j] = 0.f;
#pragma unroll
        for (int u = 0; u < 8; u++) o[j][u] = 0.f;
    }
    const float scale = 0.08838834764831845f;
    int ntile = blockIdx.x + 1;
    for (int kt = 0; kt < ntile; kt++) {
        int kb = kt * 64;
        __syncthreads();
        const float* kg = g_k + base + (size_t)kb*BT;
        const float* vg = g_v + base + (size_t)kb*BT;
#pragma unroll
        for (int i = 0; i < 8; i++) {
            int r = r0 + 8*i;
            bool ok = (kb + r) < cnt;
            float4 kv = ok ? ((const float4*)(kg + (size_t)r*BT))[c4] : make_float4(0.f,0.f,0.f,0.f);
            kst[(c4*4+0)*KST_STRIDE + r] = kv.x;
            kst[(c4*4+1)*KST_STRIDE + r] = kv.y;
            kst[(c4*4+2)*KST_STRIDE + r] = kv.z;
            kst[(c4*4+3)*KST_STRIDE + r] = kv.w;
            float4 vv = ok ? ((const float4*)(vg + (size_t)r*BT))[c4] : make_float4(0.f,0.f,0.f,0.f);
            ((float4*)(vs + r*BT))[c4] = vv;
        }
        __syncthreads();
        float s[4][4] = {};
#pragma unroll 4
        for (int kk4 = 0; kk4 < 32; kk4++) {
            float4 qa[4];
#pragma unroll
            for (int j = 0; j < 4; j++) qa[j] = ((const float4*)(qs + (ty*4+j)*BT))[kk4];
#pragma unroll
            for (int z = 0; z < 4; z++) {
                int kk = kk4*4 + z;
                float4 kb4 = *((const float4*)(kst + kk*KST_STRIDE + tx*4));
#pragma unroll
                for (int j = 0; j < 4; j++) {
                    float aj = (z == 0) ? qa[j].x : (z == 1) ? qa[j].y : (z == 2) ? qa[j].z : qa[j].w;
                    s[j][0] += aj*kb4.x; s[j][1] += aj*kb4.y;
                    s[j][2] += aj*kb4.z; s[j][3] += aj*kb4.w;
                }
            }
        }
        bool diag = (kt == blockIdx.x);
#pragma unroll
        for (int j = 0; j < 4; j++) {
            float rmax = -1e30f;
#pragma unroll
            for (int u = 0; u < 4; u++) {
                int c = tx*4 + u;
                float sv = s[j][u] * scale;
                bool valid = ((kb + c) < cnt) && (!diag || c <= ty*4 + j);
                sv = valid ? sv : -1e30f;
                s[j][u] = sv;
                rmax = fmaxf(rmax, sv);
            }
#pragma unroll
            for (int off = 8; off; off >>= 1)
                rmax = fmaxf(rmax, __shfl_xor_sync(0xffffffffu, rmax, off));
            float mnew = fmaxf(m_i[j], rmax);
            float corr = expf(m_i[j] - mnew);
            float rsum = 0.f;
#pragma unroll
            for (int u = 0; u < 4; u++) { float p = expf(s[j][u] - mnew); s[j][u] = p; rsum += p; }
#pragma unroll
            for (int off = 8; off; off >>= 1)
                rsum += __shfl_xor_sync(0xffffffffu, rsum, off);
            l_i[j] = l_i[j]*corr + rsum;
            m_i[j] = mnew;
#pragma unroll
            for (int u = 0; u < 8; u++) o[j][u] *= corr;
            *((float4*)(ps + (ty*4+j)*PS_STRIDE + tx*4)) = make_float4(s[j][0], s[j][1], s[j][2], s[j][3]);
        }
        __syncthreads();
#pragma unroll 4
        for (int j2 = 0; j2 < 64; j2++) {
            float4 v1 = ((const float4*)(vs + j2*BT))[tx];
            float4 v2 = ((const float4*)(vs + j2*BT))[16 + tx];
#pragma unroll
            for (int j = 0; j < 4; j++) {
                float p = ps[(ty*4+j)*PS_STRIDE + j2];
                o[j][0] += p*v1.x; o[j][1] += p*v1.y; o[j][2] += p*v1.z; o[j][3] += p*v1.w;
                o[j][4] += p*v2.x; o[j][5] += p*v2.y; o[j][6] += p*v2.z; o[j][7] += p*v2.w;
            }
        }
    }
    float* op = g_h + base + (size_t)rowbase*BT;
#pragma unroll
    for (int j = 0; j < 4; j++) {
        int r = ty*4 + j;
        if (rowbase + r < cnt) {
            float inv = 1.f / l_i[j];
            ((float4*)(op + (size_t)r*BT))[tx] =
                make_float4(o[j][0]*inv, o[j][1]*inv, o[j][2]*inv, o[j][3]*inv);
            ((float4*)(op + (size_t)r*BT))[16 + tx] =
                make_float4(o[j][4]*inv, o[j][5]*inv, o[j][6]*inv, o[j][7]*inv);
        }
    }
}

// ---------------- up: y = ao @ W_up[e] (K=128, N=1024 in 128-col tiles), gated ----------------
__global__ __launch_bounds__(256) void up_kernel(const float* __restrict__ Wup) {
    int rt = blockIdx.x & 15, ct = blockIdx.x >> 4;
    int e = blockIdx.y, b = blockIdx.z;
    int cnt = g_cnt[b*EE + e];
    int rowbase = rt * 128;
    if (rowbase >= cnt) return;
    int colbase = ct * 128;
    SGEMM_DECLS
    const float* A = g_h + ((size_t)(b*EE + e)*NN + rowbase)*BT;  // attn out lives in g_h
    const int* idx = g_idx + (size_t)(b*EE + e)*NN;
    const float* ap0 = (rowbase + arow0 < cnt)      ? A + (size_t)arow0*BT + ac4*4      : (const float*)0;
    const float* ap1 = (rowbase + 64 + arow0 < cnt) ? A + (size_t)(64+arow0)*BT + ac4*4 : (const float*)0;
    const float* wp = Wup + (size_t)e*BT*DD + colbase;
    float4 aR0 = ap0 ? *(const float4*)ap0 : f4zero();
    float4 aR1 = ap1 ? *(const float4*)ap1 : f4zero();
    float4 bR0 = *(const float4*)(wp + (size_t)bk0*DD + bn4*4);
    float4 bR1 = *(const float4*)(wp + (size_t)(8+bk0)*DD + bn4*4);
    const int nk = BT / GM_K;
    for (int t = 0; t < nk; t++) {
        __syncthreads();
        SGEMM_STORE_TILE(aR0, aR1, bR0, bR1)
        __syncthreads();
        if (t + 1 < nk) {
            int k0 = (t+1)*GM_K;
            aR0 = ap0 ? *(const float4*)(ap0 + k0) : f4zero();
            aR1 = ap1 ? *(const float4*)(ap1 + k0) : f4zero();
            bR0 = *(const float4*)(wp + (size_t)(k0+bk0)*DD + bn4*4);
            bR1 = *(const float4*)(wp + (size_t)(k0+8+bk0)*DD + bn4*4);
        }
        SGEMM_COMPUTE
    }
#pragma unroll
    for (int mq = 0; mq < 2; mq++)
#pragma unroll
    for (int j = 0; j < 4; j++) {
        int gr = rowbase + mq*64 + ty*4 + j;
        if (gr < cnt) {
            int tkn = idx[gr];
            float gw = g_gatew[(size_t)(b*NN + tkn)*EE + e];
            int slot = g_slot[(size_t)(b*NN + tkn)*EE + e];
            float* yp = g_ybuf + ((size_t)(b*NN + tkn)*2 + slot)*DD + colbase;
            *(float4*)&yp[tx*4]      = make_float4(gw*acc[mq][0][j][0],gw*acc[mq][0][j][1],gw*acc[mq][0][j][2],gw*acc[mq][0][j][3]);
            *(float4*)&yp[64 + tx*4] = make_float4(gw*acc[mq][1][j][0],gw*acc[mq][1][j][1],gw*acc[mq][1][j][2],gw*acc[mq][1][j][3]);
        }
    }
}

// ---------------- combine the two expert slots per token ----------------
__global__ __launch_bounds__(256) void combine_kernel(float* __restrict__ out) {
    int g = blockIdx.x * blockDim.x + threadIdx.x;
    int bt = g >> 8;
    int d4 = g & 255;
    const float4* y = (const float4*)g_ybuf;
    float4 a = y[((size_t)bt*2)*256 + d4];
    float4 bq = y[((size_t)bt*2 + 1)*256 + d4];
    float4 r;
    r.x = a.x + bq.x; r.y = a.y + bq.y; r.z = a.z + bq.z; r.w = a.w + bq.w;
    ((float4*)out)[g] = r;
}

// ---------------- launch ----------------
extern "C" void kernel_launch(void* const* d_in, const int* in_sizes, int n_in,
                              void* d_out, int out_size) {
    const float* x   = (const float*)d_in[0];
    const float* Wg  = (const float*)d_in[3];
    const float* Wd  = (const float*)d_in[4];
    const float* Wq  = (const float*)d_in[5];
    const float* Wk  = (const float*)d_in[6];
    const float* Wv  = (const float*)d_in[7];
    const float* Wup = (const float*)d_in[8];
    float* out = (float*)d_out;
    (void)in_sizes; (void)n_in;

    cudaFuncSetAttribute(attn_kernel, cudaFuncAttributeMaxDynamicSharedMemorySize,
                         ATTN_SMEM_FLOATS * (int)sizeof(float));

    zero_pmean_kernel<<<1, 32>>>();
    router_kernel<<<NTOK/8, 256>>>(x, Wg);
    compact_kernel<<<dim3(EE, BB), 256>>>();
    scalars_kernel<<<1, 32>>>(out, out_size);
    down_kernel<<<dim3(NN/128, EE, BB), 256>>>(x, Wd);
    qkv_kernel<<<dim3(NN/128, 3*EE, BB), 256>>>(Wq, Wk, Wv);
    attn_kernel<<<dim3(NN/64, EE, BB), 256, ATTN_SMEM_FLOATS * (int)sizeof(float)>>>();
    up_kernel<<<dim3((NN/128)*(DD/128), EE, BB), 256>>>(Wup);
    combine_kernel<<<(NTOK*DD/4)/256, 256>>>(out);
}